// round 9
// baseline (speedup 1.0000x reference)
#include <cuda_runtime.h>
#include <cuda_fp16.h>
#include <cstdint>

#define NCLS 4
#define VMX 64
#define NF 28
#define HID 64
#define OUTF 768
#define NBINS (NCLS*VMX*NF)   // 7168
#define RBH 64
#define NMAX 100096
#define MTILE 128
#define NTILE 128

typedef unsigned long long ull;

// static scratch (no allocations allowed)
__device__ int   g_counts[NBINS];
__device__ float g_prob[NBINS];
__device__ __align__(16) __half g_hf[(size_t)NMAX * HID];   // h (fp16)
__device__ __align__(16) __half g_wf[OUTF * HID];           // W_fc (fp16)

// ---------------- prologue kernels ----------------
__global__ void prep_kernel(const float* __restrict__ W) {
    int i = blockIdx.x * blockDim.x + threadIdx.x;
    if (i < NBINS) g_counts[i] = 0;
    if (i < OUTF * HID) g_wf[i] = __float2half(W[i]);
}

__global__ void hist_kernel(const float* __restrict__ VS,
                            const int* __restrict__ Level, int N) {
    __shared__ int s_counts[NBINS];
    for (int i = threadIdx.x; i < NBINS; i += blockDim.x) s_counts[i] = 0;
    __syncthreads();
    int stride = gridDim.x * blockDim.x;
    for (int r = blockIdx.x * blockDim.x + threadIdx.x; r < N; r += stride) {
        int lev = Level[r];
        int base = lev * VMX;
        const float4* vrow = (const float4*)(VS + (size_t)r * NF);
#pragma unroll
        for (int q = 0; q < 7; q++) {
            float4 v = vrow[q];
            atomicAdd(&s_counts[(base + (int)v.x) * NF + 4*q + 0], 1);
            atomicAdd(&s_counts[(base + (int)v.y) * NF + 4*q + 1], 1);
            atomicAdd(&s_counts[(base + (int)v.z) * NF + 4*q + 2], 1);
            atomicAdd(&s_counts[(base + (int)v.w) * NF + 4*q + 3], 1);
        }
    }
    __syncthreads();
    for (int i = threadIdx.x; i < NBINS; i += blockDim.x)
        if (s_counts[i]) atomicAdd(&g_counts[i], s_counts[i]);
}

__global__ void prob_kernel() {
    __shared__ float cls_sz[NCLS];
    int t = threadIdx.x;
    if (t < NCLS) cls_sz[t] = 0.0f;
    __syncthreads();
    atomicAdd(&cls_sz[t >> 6], (float)g_counts[t * NF]);
    __syncthreads();
    for (int j = t; j < NBINS; j += 256) {
        int cls = j / (VMX * NF);
        g_prob[j] = (float)g_counts[j] / cls_sz[cls];
    }
}

// ---------------- helpers ----------------
__device__ __forceinline__ float fast_sig(float x) {
    return 1.0f / (1.0f + __expf(-x));
}
__device__ __forceinline__ void unpack2(ull p, float& lo, float& hi) {
    asm("mov.b64 {%0, %1}, %2;" : "=f"(lo), "=f"(hi) : "l"(p));
}
__device__ __forceinline__ uint32_t smem_u32(const void* p) {
    uint32_t a;
    asm("{ .reg .u64 t; cvta.to.shared.u64 t, %1; cvt.u32.u64 %0, t; }"
        : "=r"(a) : "l"(p));
    return a;
}
__device__ __forceinline__ void ldsm4(uint32_t addr, uint32_t* r) {
    asm volatile("ldmatrix.sync.aligned.m8n8.x4.shared.b16 {%0,%1,%2,%3}, [%4];"
        : "=r"(r[0]), "=r"(r[1]), "=r"(r[2]), "=r"(r[3]) : "r"(addr));
}
__device__ __forceinline__ void mma_f16(float* c, const uint32_t* a,
                                        uint32_t b0, uint32_t b1) {
    asm volatile(
        "mma.sync.aligned.m16n8k16.row.col.f32.f16.f16.f32 "
        "{%0,%1,%2,%3}, {%4,%5,%6,%7}, {%8,%9}, {%0,%1,%2,%3};"
        : "+f"(c[0]), "+f"(c[1]), "+f"(c[2]), "+f"(c[3])
        : "r"(a[0]), "r"(a[1]), "r"(a[2]), "r"(a[3]), "r"(b0), "r"(b1));
}

// ---------------- h kernel: gates + activations + CC copy (overlap) ----------------
#define HK_SMEM (32*NF*8 + 32*192*8)   // 7168 + 49152 = 56320

__global__ __launch_bounds__(192)
void h_kernel(const float* __restrict__ VS,
              const int* __restrict__ Level,
              const int* __restrict__ Depart,
              const float* __restrict__ W_ih,
              const float* __restrict__ b_ih,
              const float* __restrict__ b_hh,
              const float* __restrict__ CC,
              float* __restrict__ cc_out,
              float* __restrict__ lev_out,
              float* __restrict__ dep_out,
              int N)
{
    extern __shared__ char hsm[];
    ull* x2 = (ull*)hsm;                 // [32 row-pairs][28]
    ull* g2 = (ull*)(hsm + 32*NF*8);     // [32 row-pairs][192 gate-cols]
    __shared__ int lev_s[RBH];

    const int t = threadIdx.x;
    const int row0 = blockIdx.x * RBH;

    if (t < RBH) {
        int r = row0 + t;
        int lv = (r < N) ? Level[r] : 0;
        lev_s[t] = lv;
        if (r < N) { lev_out[r] = (float)lv; dep_out[r] = (float)Depart[r]; }
    }
    __syncthreads();

    // x = VS * prob, packed as row pairs
    for (int i = t; i < RBH * NF; i += 192) {
        int r = i / NF, c = i % NF;
        float xv = 0.0f;
        if (row0 + r < N) {
            float v = VS[(size_t)(row0 + r) * NF + c];
            int lev = lev_s[r];
            xv = v * g_prob[(lev * VMX + (int)v) * NF + c];
        }
        ((float*)&x2[(r >> 1) * NF + c])[r & 1] = xv;
    }
    __syncthreads();

    // gates: thread t owns gate column c (i,g,o; f skipped since c0=0).
    {
        int c = (t < 64) ? t : t + 64;
        float w[NF];
#pragma unroll
        for (int k = 0; k < NF; k++) w[k] = W_ih[c * NF + k];
        float b = b_ih[c] + b_hh[c];
#pragma unroll 2
        for (int rp = 0; rp < 32; rp += 2) {
            float a0l = b, a0h = b, a1l = b, a1h = b;
#pragma unroll
            for (int k = 0; k < NF; k++) {
                float x0l, x0h, x1l, x1h;
                unpack2(x2[rp * NF + k], x0l, x0h);
                unpack2(x2[(rp + 1) * NF + k], x1l, x1h);
                a0l += w[k] * x0l; a0h += w[k] * x0h;
                a1l += w[k] * x1l; a1h += w[k] * x1h;
            }
            *(float2*)&g2[rp * 192 + t]       = make_float2(a0l, a0h);
            *(float2*)&g2[(rp + 1) * 192 + t] = make_float2(a1l, a1h);
        }
    }
    __syncthreads();

    // activations -> g_hf
    {
        const float* gf = (const float*)g2;
        for (int i = t; i < RBH * HID; i += 192) {
            int r = i >> 6, u = i & 63;
            int base = ((r >> 1) * 192) * 2 + (r & 1);
            float gi = gf[base + u * 2];
            float gg = gf[base + (64 + u) * 2];
            float go = gf[base + (128 + u) * 2];
            float cv = fast_sig(gi) * tanhf(gg);
            float h = fast_sig(go) * tanhf(cv);
            if (row0 + r < N) g_hf[(size_t)(row0 + r) * HID + u] = __float2half(h);
        }
    }

    // CC copy for this block's 64 rows (overlaps other blocks' compute).
    // no barrier needed: independent of smem state.
    {
        int nrow = (row0 + RBH <= N) ? RBH : (N > row0 ? N - row0 : 0);
        int total = nrow * (OUTF / 4);
        const float4* src = (const float4*)(CC + (size_t)row0 * OUTF);
        float4* dst = (float4*)(cc_out + (size_t)row0 * OUTF);
#pragma unroll 4
        for (int i = t; i < total; i += 192) dst[i] = src[i];
    }
}

// ---------------- gemm kernel: fp16 mma.sync ----------------
// smem: A[kc(4)][r(128)][48B], B[kc(4)][n(128)][48B], bias
#define KCB 6144    // 128*48
#define A_OFF 0
#define B_OFF 24576
#define S_BIAS 49152
#define GEMM_SMEM 49664

__global__ __launch_bounds__(256, 2)
void gemm_kernel(const float* __restrict__ b_fc,
                 float* __restrict__ vs_out,
                 int N)
{
    extern __shared__ char sm[];
    const int t = threadIdx.x;
    const int bid = blockIdx.x;
    const int sub = bid % 6;
    const int row0 = (bid / 6) * MTILE;

    const int lane = t & 31;
    const int wm = t >> 5;
    const int ctb = sub * NTILE;
    const uint32_t sb = smem_u32(sm);

    // bias
    if (t < 32) ((float4*)(sm + S_BIAS))[t] = ((const float4*)(b_fc + ctb))[t];

    // A fill: q = 16B chunk 0..7 -> kc = q>>1, hf = q&1
#pragma unroll
    for (int j = 0; j < 4; j++) {
        int i = t + j * 256;
        int r = i >> 3, q = i & 7;
        int kc = q >> 1, hf = q & 1;
        uint4 v = make_uint4(0, 0, 0, 0);
        if (row0 + r < N)
            v = ((const uint4*)(g_hf + (size_t)(row0 + r) * HID))[q];
        *(uint4*)(sm + A_OFF + kc * KCB + r * 48 + hf * 16) = v;
    }
    // B fill
#pragma unroll
    for (int j = 0; j < 4; j++) {
        int i = t + j * 256;
        int n = i >> 3, q = i & 7;
        int kc = q >> 1, hf = q & 1;
        *(uint4*)(sm + B_OFF + kc * KCB + n * 48 + hf * 16) =
            ((const uint4*)(g_wf + (size_t)(ctb + n) * HID))[q];
    }
    __syncthreads();

    // accumulators: 16 n-tiles x 4, init with bias
    float acc[16][4];
    {
        const float* bs = (const float*)(sm + S_BIAS);
        int cb = (lane & 3) * 2;
#pragma unroll
        for (int nt = 0; nt < 16; nt++) {
            float b0 = bs[nt * 8 + cb], b1 = bs[nt * 8 + cb + 1];
            acc[nt][0] = b0; acc[nt][1] = b1; acc[nt][2] = b0; acc[nt][3] = b1;
        }
    }

    const int rowb = wm * 16;
    const uint32_t a_lane_off = (uint32_t)((rowb + (lane & 15)) * 48 + ((lane & 16) ? 16 : 0));
    const uint32_t b_row_off  = (uint32_t)((lane & 7) * 48 + ((lane & 8) ? 16 : 0));
    const uint32_t b_kc_sel   = (uint32_t)(((lane >> 4) & 1) * KCB);

#pragma unroll
    for (int p = 0; p < 2; p++) {
        uint32_t A[2][4];
#pragma unroll
        for (int j = 0; j < 2; j++)
            ldsm4(sb + A_OFF + (2 * p + j) * KCB + a_lane_off, A[j]);
#pragma unroll
        for (int nt = 0; nt < 16; nt++) {
            uint32_t B[4];
            uint32_t boff = 2 * p * KCB + b_kc_sel + (uint32_t)(nt * 8 * 48) + b_row_off;
            ldsm4(sb + B_OFF + boff, B);
            mma_f16(acc[nt], A[0], B[0], B[1]);
            mma_f16(acc[nt], A[1], B[2], B[3]);
        }
    }

    // epilogue: STG.64 (each 4-lane group covers a full 32B sector)
    {
        int r_lo = row0 + rowb + (lane >> 2);
        int r_hi = r_lo + 8;
        int cb = ctb + (lane & 3) * 2;
#pragma unroll
        for (int nt = 0; nt < 16; nt++) {
            if (r_lo < N)
                *(float2*)(vs_out + (size_t)r_lo * OUTF + cb + nt * 8) =
                    make_float2(acc[nt][0], acc[nt][1]);
            if (r_hi < N)
                *(float2*)(vs_out + (size_t)r_hi * OUTF + cb + nt * 8) =
                    make_float2(acc[nt][2], acc[nt][3]);
        }
    }
}

extern "C" void kernel_launch(void* const* d_in, const int* in_sizes, int n_in,
                              void* d_out, int out_size) {
    const float* VS     = (const float*)d_in[0];
    const float* CC     = (const float*)d_in[1];
    const int*   Level  = (const int*)d_in[2];
    const int*   Depart = (const int*)d_in[3];
    const float* W_ih   = (const float*)d_in[4];
    // d_in[5] = W_hh, unused (h0 = 0)
    const float* b_ih   = (const float*)d_in[6];
    const float* b_hh   = (const float*)d_in[7];
    const float* W_fc   = (const float*)d_in[8];
    const float* b_fc   = (const float*)d_in[9];

    int N = in_sizes[0] / NF;

    float* out = (float*)d_out;
    float* cc_out  = out;
    float* vs_out  = out + (size_t)N * OUTF;
    float* lev_out = out + (size_t)2 * N * OUTF;
    float* dep_out = lev_out + N;

    static int attr_set = 0;
    if (!attr_set) {
        cudaFuncSetAttribute(h_kernel,
                             cudaFuncAttributeMaxDynamicSharedMemorySize, HK_SMEM);
        cudaFuncSetAttribute(gemm_kernel,
                             cudaFuncAttributeMaxDynamicSharedMemorySize, GEMM_SMEM);
        attr_set = 1;
    }

    prep_kernel<<<(OUTF * HID + 255) / 256, 256>>>(W_fc);
    hist_kernel<<<148, 256>>>(VS, Level, N);
    prob_kernel<<<1, 256>>>();
    h_kernel<<<(N + RBH - 1) / RBH, 192, HK_SMEM>>>(
        VS, Level, Depart, W_ih, b_ih, b_hh, CC, cc_out, lev_out, dep_out, N);
    int nstrip = (N + MTILE - 1) / MTILE;
    gemm_kernel<<<nstrip * 6, 256, GEMM_SMEM>>>(b_fc, vs_out, N);
}

// round 10
// speedup vs baseline: 1.0991x; 1.0991x over previous
#include <cuda_runtime.h>
#include <cuda_fp16.h>
#include <cstdint>

#define NCLS 4
#define VMX 64
#define NF 28
#define HID 64
#define OUTF 768
#define NBINS (NCLS*VMX*NF)   // 7168
#define RBH 64
#define NMAX 100096
#define MTILE 128
#define NTILE 128

typedef unsigned long long ull;

// static scratch (no allocations allowed)
__device__ int   g_counts[NBINS];
__device__ float g_prob[NBINS];
__device__ __align__(16) __half g_hf[(size_t)NMAX * HID];   // h (fp16)
__device__ __align__(16) __half g_wf[OUTF * HID];           // W_fc (fp16)

// ---------------- prologue kernels ----------------
__global__ void prep_kernel(const float* __restrict__ W) {
    int i = blockIdx.x * blockDim.x + threadIdx.x;
    if (i < NBINS) g_counts[i] = 0;
    if (i < OUTF * HID) g_wf[i] = __float2half(W[i]);
}

__global__ void hist_kernel(const float* __restrict__ VS,
                            const int* __restrict__ Level, int N) {
    __shared__ int s_counts[NBINS];
    for (int i = threadIdx.x; i < NBINS; i += blockDim.x) s_counts[i] = 0;
    __syncthreads();
    int stride = gridDim.x * blockDim.x;
    for (int r = blockIdx.x * blockDim.x + threadIdx.x; r < N; r += stride) {
        int lev = Level[r];
        int base = lev * VMX;
        const float4* vrow = (const float4*)(VS + (size_t)r * NF);
#pragma unroll
        for (int q = 0; q < 7; q++) {
            float4 v = vrow[q];
            atomicAdd(&s_counts[(base + (int)v.x) * NF + 4*q + 0], 1);
            atomicAdd(&s_counts[(base + (int)v.y) * NF + 4*q + 1], 1);
            atomicAdd(&s_counts[(base + (int)v.z) * NF + 4*q + 2], 1);
            atomicAdd(&s_counts[(base + (int)v.w) * NF + 4*q + 3], 1);
        }
    }
    __syncthreads();
    for (int i = threadIdx.x; i < NBINS; i += blockDim.x)
        if (s_counts[i]) atomicAdd(&g_counts[i], s_counts[i]);
}

__global__ void prob_kernel() {
    __shared__ float cls_sz[NCLS];
    int t = threadIdx.x;
    if (t < NCLS) cls_sz[t] = 0.0f;
    __syncthreads();
    atomicAdd(&cls_sz[t >> 6], (float)g_counts[t * NF]);
    __syncthreads();
    for (int j = t; j < NBINS; j += 256) {
        int cls = j / (VMX * NF);
        g_prob[j] = (float)g_counts[j] / cls_sz[cls];
    }
}

// ---------------- helpers ----------------
__device__ __forceinline__ float sig_t(float x) {      // sigmoid via MUFU.TANH
    return 0.5f * tanhf(0.5f * x) + 0.5f;
}
__device__ __forceinline__ void unpack2(ull p, float& lo, float& hi) {
    asm("mov.b64 {%0, %1}, %2;" : "=f"(lo), "=f"(hi) : "l"(p));
}
__device__ __forceinline__ uint32_t smem_u32(const void* p) {
    uint32_t a;
    asm("{ .reg .u64 t; cvta.to.shared.u64 t, %1; cvt.u32.u64 %0, t; }"
        : "=r"(a) : "l"(p));
    return a;
}
__device__ __forceinline__ void ldsm4(uint32_t addr, uint32_t* r) {
    asm volatile("ldmatrix.sync.aligned.m8n8.x4.shared.b16 {%0,%1,%2,%3}, [%4];"
        : "=r"(r[0]), "=r"(r[1]), "=r"(r[2]), "=r"(r[3]) : "r"(addr));
}
__device__ __forceinline__ void mma_f16(float* c, const uint32_t* a,
                                        uint32_t b0, uint32_t b1) {
    asm volatile(
        "mma.sync.aligned.m16n8k16.row.col.f32.f16.f16.f32 "
        "{%0,%1,%2,%3}, {%4,%5,%6,%7}, {%8,%9}, {%0,%1,%2,%3};"
        : "+f"(c[0]), "+f"(c[1]), "+f"(c[2]), "+f"(c[3])
        : "r"(a[0]), "r"(a[1]), "r"(a[2]), "r"(a[3]), "r"(b0), "r"(b1));
}

// ---------------- h kernel: compute blocks + interleaved CC-copy blocks ----------------
// bid % 3 == 2 -> copy block (128 CC rows); else compute block (64 rows).
#define HK_SMEM (32*NF*8 + 32*192*8)   // 7168 + 49152 = 56320

__global__ __launch_bounds__(192)
void h_kernel(const float* __restrict__ VS,
              const int* __restrict__ Level,
              const int* __restrict__ Depart,
              const float* __restrict__ W_ih,
              const float* __restrict__ b_ih,
              const float* __restrict__ b_hh,
              const float* __restrict__ CC,
              float* __restrict__ cc_out,
              float* __restrict__ lev_out,
              float* __restrict__ dep_out,
              int N)
{
    const int t = threadIdx.x;
    const int bid = blockIdx.x;

    // ---- copy blocks: pure CC streaming, co-resident with compute blocks ----
    if (bid % 3 == 2) {
        int cid = bid / 3;
        int crow0 = cid * 128;
        int nrow = (crow0 + 128 <= N) ? 128 : (N > crow0 ? N - crow0 : 0);
        int total = nrow * (OUTF / 4);
        const float4* src = (const float4*)(CC + (size_t)crow0 * OUTF);
        float4* dst = (float4*)(cc_out + (size_t)crow0 * OUTF);
#pragma unroll 4
        for (int i = t; i < total; i += 192) dst[i] = src[i];
        return;
    }

    // ---- compute blocks ----
    const int hid = (bid / 3) * 2 + (bid % 3);
    const int row0 = hid * RBH;
    if (row0 >= N) return;

    extern __shared__ char hsm[];
    ull* x2 = (ull*)hsm;                 // [32 row-pairs][28]
    ull* g2 = (ull*)(hsm + 32*NF*8);     // [32 row-pairs][192 gate-cols]
    __shared__ int lev_s[RBH];

    if (t < RBH) {
        int r = row0 + t;
        int lv = (r < N) ? Level[r] : 0;
        lev_s[t] = lv;
        if (r < N) { lev_out[r] = (float)lv; dep_out[r] = (float)Depart[r]; }
    }
    __syncthreads();

    // x = VS * prob, packed as row pairs
    for (int i = t; i < RBH * NF; i += 192) {
        int r = i / NF, c = i % NF;
        float xv = 0.0f;
        if (row0 + r < N) {
            float v = VS[(size_t)(row0 + r) * NF + c];
            int lev = lev_s[r];
            xv = v * g_prob[(lev * VMX + (int)v) * NF + c];
        }
        ((float*)&x2[(r >> 1) * NF + c])[r & 1] = xv;
    }
    __syncthreads();

    // gates: thread t owns gate column c (i,g,o; f skipped since c0=0).
    {
        int c = (t < 64) ? t : t + 64;
        float w[NF];
#pragma unroll
        for (int k = 0; k < NF; k++) w[k] = W_ih[c * NF + k];
        float b = b_ih[c] + b_hh[c];
#pragma unroll 2
        for (int rp = 0; rp < 32; rp += 2) {
            float a0l = b, a0h = b, a1l = b, a1h = b;
#pragma unroll
            for (int k = 0; k < NF; k++) {
                float x0l, x0h, x1l, x1h;
                unpack2(x2[rp * NF + k], x0l, x0h);
                unpack2(x2[(rp + 1) * NF + k], x1l, x1h);
                a0l += w[k] * x0l; a0h += w[k] * x0h;
                a1l += w[k] * x1l; a1h += w[k] * x1h;
            }
            *(float2*)&g2[rp * 192 + t]       = make_float2(a0l, a0h);
            *(float2*)&g2[(rp + 1) * 192 + t] = make_float2(a1l, a1h);
        }
    }
    __syncthreads();

    // activations -> g_hf
    {
        const float* gf = (const float*)g2;
        for (int i = t; i < RBH * HID; i += 192) {
            int r = i >> 6, u = i & 63;
            int base = ((r >> 1) * 192) * 2 + (r & 1);
            float gi = gf[base + u * 2];
            float gg = gf[base + (64 + u) * 2];
            float go = gf[base + (128 + u) * 2];
            float cv = sig_t(gi) * tanhf(gg);
            float h = sig_t(go) * tanhf(cv);
            if (row0 + r < N) g_hf[(size_t)(row0 + r) * HID + u] = __float2half(h);
        }
    }
}

// ---------------- gemm kernel: fp16 mma.sync ----------------
// smem: A[kc(4)][r(128)][48B], B[kc(4)][n(128)][48B], bias
#define KCB 6144    // 128*48
#define A_OFF 0
#define B_OFF 24576
#define S_BIAS 49152
#define GEMM_SMEM 49664

__global__ __launch_bounds__(256, 2)
void gemm_kernel(const float* __restrict__ b_fc,
                 float* __restrict__ vs_out,
                 int N)
{
    extern __shared__ char sm[];
    const int t = threadIdx.x;
    const int bid = blockIdx.x;
    const int sub = bid % 6;
    const int row0 = (bid / 6) * MTILE;

    const int lane = t & 31;
    const int wm = t >> 5;
    const int ctb = sub * NTILE;
    const uint32_t sb = smem_u32(sm);

    // bias
    if (t < 32) ((float4*)(sm + S_BIAS))[t] = ((const float4*)(b_fc + ctb))[t];

    // A fill: q = 16B chunk 0..7 -> kc = q>>1, hf = q&1
#pragma unroll
    for (int j = 0; j < 4; j++) {
        int i = t + j * 256;
        int r = i >> 3, q = i & 7;
        int kc = q >> 1, hf = q & 1;
        uint4 v = make_uint4(0, 0, 0, 0);
        if (row0 + r < N)
            v = ((const uint4*)(g_hf + (size_t)(row0 + r) * HID))[q];
        *(uint4*)(sm + A_OFF + kc * KCB + r * 48 + hf * 16) = v;
    }
    // B fill
#pragma unroll
    for (int j = 0; j < 4; j++) {
        int i = t + j * 256;
        int n = i >> 3, q = i & 7;
        int kc = q >> 1, hf = q & 1;
        *(uint4*)(sm + B_OFF + kc * KCB + n * 48 + hf * 16) =
            ((const uint4*)(g_wf + (size_t)(ctb + n) * HID))[q];
    }
    __syncthreads();

    // accumulators: 16 n-tiles x 4, init with bias
    float acc[16][4];
    {
        const float* bs = (const float*)(sm + S_BIAS);
        int cb = (lane & 3) * 2;
#pragma unroll
        for (int nt = 0; nt < 16; nt++) {
            float b0 = bs[nt * 8 + cb], b1 = bs[nt * 8 + cb + 1];
            acc[nt][0] = b0; acc[nt][1] = b1; acc[nt][2] = b0; acc[nt][3] = b1;
        }
    }

    const int rowb = wm * 16;
    const uint32_t a_lane_off = (uint32_t)((rowb + (lane & 15)) * 48 + ((lane & 16) ? 16 : 0));
    const uint32_t b_row_off  = (uint32_t)((lane & 7) * 48 + ((lane & 8) ? 16 : 0));
    const uint32_t b_kc_sel   = (uint32_t)(((lane >> 4) & 1) * KCB);

#pragma unroll
    for (int p = 0; p < 2; p++) {
        uint32_t A[2][4];
#pragma unroll
        for (int j = 0; j < 2; j++)
            ldsm4(sb + A_OFF + (2 * p + j) * KCB + a_lane_off, A[j]);
#pragma unroll
        for (int nt = 0; nt < 16; nt++) {
            uint32_t B[4];
            uint32_t boff = 2 * p * KCB + b_kc_sel + (uint32_t)(nt * 8 * 48) + b_row_off;
            ldsm4(sb + B_OFF + boff, B);
            mma_f16(acc[nt], A[0], B[0], B[1]);
            mma_f16(acc[nt], A[1], B[2], B[3]);
        }
    }

    // epilogue: STG.64 (each 4-lane group covers a full 32B sector)
    {
        int r_lo = row0 + rowb + (lane >> 2);
        int r_hi = r_lo + 8;
        int cb = ctb + (lane & 3) * 2;
#pragma unroll
        for (int nt = 0; nt < 16; nt++) {
            if (r_lo < N)
                *(float2*)(vs_out + (size_t)r_lo * OUTF + cb + nt * 8) =
                    make_float2(acc[nt][0], acc[nt][1]);
            if (r_hi < N)
                *(float2*)(vs_out + (size_t)r_hi * OUTF + cb + nt * 8) =
                    make_float2(acc[nt][2], acc[nt][3]);
        }
    }
}

extern "C" void kernel_launch(void* const* d_in, const int* in_sizes, int n_in,
                              void* d_out, int out_size) {
    const float* VS     = (const float*)d_in[0];
    const float* CC     = (const float*)d_in[1];
    const int*   Level  = (const int*)d_in[2];
    const int*   Depart = (const int*)d_in[3];
    const float* W_ih   = (const float*)d_in[4];
    // d_in[5] = W_hh, unused (h0 = 0)
    const float* b_ih   = (const float*)d_in[6];
    const float* b_hh   = (const float*)d_in[7];
    const float* W_fc   = (const float*)d_in[8];
    const float* b_fc   = (const float*)d_in[9];

    int N = in_sizes[0] / NF;

    float* out = (float*)d_out;
    float* cc_out  = out;
    float* vs_out  = out + (size_t)N * OUTF;
    float* lev_out = out + (size_t)2 * N * OUTF;
    float* dep_out = lev_out + N;

    static int attr_set = 0;
    if (!attr_set) {
        cudaFuncSetAttribute(h_kernel,
                             cudaFuncAttributeMaxDynamicSharedMemorySize, HK_SMEM);
        cudaFuncSetAttribute(gemm_kernel,
                             cudaFuncAttributeMaxDynamicSharedMemorySize, GEMM_SMEM);
        attr_set = 1;
    }

    prep_kernel<<<(OUTF * HID + 255) / 256, 256>>>(W_fc);
    hist_kernel<<<148, 256>>>(VS, Level, N);
    prob_kernel<<<1, 256>>>();
    // grid: 2 compute blocks (64 rows each) : 1 copy block (128 rows)
    int ncopy = (N + 127) / 128;            // 782
    h_kernel<<<ncopy * 3, 192, HK_SMEM>>>(
        VS, Level, Depart, W_ih, b_ih, b_hh, CC, cc_out, lev_out, dep_out, N);
    int nstrip = (N + MTILE - 1) / MTILE;
    gemm_kernel<<<nstrip * 6, 256, GEMM_SMEM>>>(b_fc, vs_out, N);
}